// round 4
// baseline (speedup 1.0000x reference)
#include <cuda_runtime.h>
#include <cstdint>

#define BATCH       8192
#define FEAT_DIM    2048
#define NUM_CLASSES 751
#define TPB         256

// Scratch (device globals; allocation forbidden)
__device__ float        g_rowdist[BATCH];
__device__ unsigned int g_done_count;   // zero at load; last block resets

__global__ void __launch_bounds__(TPB, 8)
center_loss_kernel(const float* __restrict__ x,
                   const int*   __restrict__ labels_i32,
                   const float* __restrict__ centers,
                   float*       __restrict__ out) {
    const int b    = blockIdx.x;
    const int tid  = threadIdx.x;
    const int lane = tid & 31;
    const int wid  = tid >> 5;

    // ---- x loads are label-independent: declare them first so ptxas can
    //      front-batch them before the detection chain resolves ----
    const float4* __restrict__ xr = (const float4*)(x + (size_t)b * FEAT_DIM);
    float4 a0 = __ldg(xr + tid);
    float4 a1 = __ldg(xr + tid + TPB);

    // ---- barrier-free label-width detection (per warp, ballot only) ----
    // int64 LE: odd int32 words of first 16 pairs are high halves of values
    // in [0,751) -> all zero. int32: P(16 consecutive labels == 0) ~ 0.
    int hi = (lane < 16) ? __ldg(labels_i32 + 2 * lane + 1) : 0;
    unsigned nz = __ballot_sync(0xFFFFFFFFu, hi != 0);
    const int lbl = __ldg(labels_i32 + ((nz == 0u) ? 2 * b : b));

    const float4* __restrict__ cr = (const float4*)(centers + (size_t)lbl * FEAT_DIM);
    float4 c0 = __ldg(cr + tid);
    float4 c1 = __ldg(cr + tid + TPB);

    float d, acc;
    d = a0.x - c0.x; acc  = d * d;
    d = a0.y - c0.y; acc += d * d;
    d = a0.z - c0.z; acc += d * d;
    d = a0.w - c0.w; acc += d * d;
    d = a1.x - c1.x; acc += d * d;
    d = a1.y - c1.y; acc += d * d;
    d = a1.z - c1.z; acc += d * d;
    d = a1.w - c1.w; acc += d * d;

    #pragma unroll
    for (int off = 16; off > 0; off >>= 1)
        acc += __shfl_down_sync(0xFFFFFFFFu, acc, off);

    __shared__ float s_warp[TPB / 32];
    if (lane == 0) s_warp[wid] = acc;
    __syncthreads();

    __shared__ bool s_is_last;
    if (tid == 0) {
        float v = 0.0f;
        #pragma unroll
        for (int w = 0; w < TPB / 32; w++) v += s_warp[w];    // fixed order
        v = fminf(fmaxf(v, 1e-12f), 1e12f);                   // clamp as ref
        g_rowdist[b] = v;
        __threadfence();
        unsigned int prev = atomicAdd(&g_done_count, 1u);
        s_is_last = (prev == (unsigned int)(BATCH - 1));
    }
    __syncthreads();

    // ---- last block: deterministic fixed-order reduction of 8192 partials ----
    if (s_is_last) {
        float lacc = 0.0f;
        #pragma unroll
        for (int i = tid; i < BATCH; i += TPB)   // 32 per thread, fixed order
            lacc += g_rowdist[i];

        #pragma unroll
        for (int off = 16; off > 0; off >>= 1)
            lacc += __shfl_down_sync(0xFFFFFFFFu, lacc, off);

        __shared__ float s_fin[TPB / 32];
        if (lane == 0) s_fin[wid] = lacc;
        __syncthreads();

        if (tid == 0) {
            float total = 0.0f;
            #pragma unroll
            for (int w = 0; w < TPB / 32; w++) total += s_fin[w];
            const float clipped_zeros =
                (float)BATCH * (float)(NUM_CLASSES - 1) * 1e-12f;
            out[0] = (total + clipped_zeros) / (float)BATCH;
            g_done_count = 0;                    // reset for graph replay
        }
    }
}

extern "C" void kernel_launch(void* const* d_in, const int* in_sizes, int n_in,
                              void* d_out, int out_size) {
    const float* x       = (const float*)d_in[0];
    const int*   labels  = (const int*)d_in[1];   // width detected in-kernel
    const float* centers = (const float*)d_in[2];
    float*       out     = (float*)d_out;

    center_loss_kernel<<<BATCH, TPB>>>(x, labels, centers, out);
}

// round 5
// speedup vs baseline: 1.4320x; 1.4320x over previous
#include <cuda_runtime.h>
#include <cstdint>

#define BATCH       8192
#define FEAT_DIM    2048
#define NUM_CLASSES 751
#define TPB         256
#define NBLK        592                       // 4 blocks/SM * 148 SMs, one wave
#define NWARPS      (NBLK * (TPB / 32))       // 4736 warps; rows per warp: 1-2

__device__ float        g_partial[NBLK];
__device__ unsigned int g_done_count;         // zero at load; last block resets

__global__ void __launch_bounds__(TPB, 4)
center_loss_kernel(const float* __restrict__ x,
                   const int*   __restrict__ labels_i32,
                   const float* __restrict__ centers,
                   float*       __restrict__ out) {
    const int tid  = threadIdx.x;
    const int lane = tid & 31;
    const int wid  = tid >> 5;
    const int gw   = blockIdx.x * (TPB / 32) + wid;   // global warp id

    // ---- barrier-free label-width detection (ballot, L1-hot 128B) ----
    // int64 LE: odd int32 words of first 16 pairs (labels in [0,751)) are 0.
    int hiw = (lane < 16) ? __ldg(labels_i32 + 2 * lane + 1) : 0;
    const bool is_i64 = (__ballot_sync(0xFFFFFFFFu, hiw != 0) == 0u);

    // ---- grid-stride over rows, one row per warp per iteration ----
    float wsum = 0.0f;                         // fixed-order per-warp running sum
    for (int r = gw; r < BATCH; r += NWARPS) {
        const int lbl = __ldg(labels_i32 + (is_i64 ? 2 * r : r));
        const float4* __restrict__ xr = (const float4*)(x       + (size_t)r   * FEAT_DIM);
        const float4* __restrict__ cr = (const float4*)(centers + (size_t)lbl * FEAT_DIM);

        float acc = 0.0f;
        #pragma unroll
        for (int j = 0; j < 4; j++) {          // 4 chunks of 4 float4-pairs
            float4 a0 = __ldg(xr + lane + 32 * (4 * j + 0));
            float4 a1 = __ldg(xr + lane + 32 * (4 * j + 1));
            float4 a2 = __ldg(xr + lane + 32 * (4 * j + 2));
            float4 a3 = __ldg(xr + lane + 32 * (4 * j + 3));
            float4 c0 = __ldg(cr + lane + 32 * (4 * j + 0));
            float4 c1 = __ldg(cr + lane + 32 * (4 * j + 1));
            float4 c2 = __ldg(cr + lane + 32 * (4 * j + 2));
            float4 c3 = __ldg(cr + lane + 32 * (4 * j + 3));
            float d;
            d = a0.x - c0.x; acc += d * d;  d = a0.y - c0.y; acc += d * d;
            d = a0.z - c0.z; acc += d * d;  d = a0.w - c0.w; acc += d * d;
            d = a1.x - c1.x; acc += d * d;  d = a1.y - c1.y; acc += d * d;
            d = a1.z - c1.z; acc += d * d;  d = a1.w - c1.w; acc += d * d;
            d = a2.x - c2.x; acc += d * d;  d = a2.y - c2.y; acc += d * d;
            d = a2.z - c2.z; acc += d * d;  d = a2.w - c2.w; acc += d * d;
            d = a3.x - c3.x; acc += d * d;  d = a3.y - c3.y; acc += d * d;
            d = a3.z - c3.z; acc += d * d;  d = a3.w - c3.w; acc += d * d;
        }

        // butterfly reduce -> every lane holds the row total
        #pragma unroll
        for (int off = 16; off > 0; off >>= 1)
            acc += __shfl_xor_sync(0xFFFFFFFFu, acc, off);

        wsum += fminf(fmaxf(acc, 1e-12f), 1e12f);   // clamp as reference
    }

    // ---- per-block combine (fixed order), publish with acq_rel atomic ----
    __shared__ float s_w[TPB / 32];
    if (lane == 0) s_w[wid] = wsum;
    __syncthreads();

    __shared__ bool s_is_last;
    if (tid == 0) {
        float p = 0.0f;
        #pragma unroll
        for (int w = 0; w < TPB / 32; w++) p += s_w[w];
        g_partial[blockIdx.x] = p;            // normal STG (reaches L2)
        unsigned int prev;
        // release: orders the partial store; acquire: makes all partials
        // visible to the winning (last) block. No MEMBAR, no CCTL.IVALL spam.
        asm volatile("atom.acq_rel.gpu.global.add.u32 %0, [%1], %2;"
                     : "=r"(prev)
                     : "l"(&g_done_count), "r"(1u)
                     : "memory");
        s_is_last = (prev == (unsigned int)(NBLK - 1));
    }
    __syncthreads();

    // ---- last block: deterministic fixed-order reduction of 592 partials ----
    if (s_is_last) {
        float lacc = 0.0f;
        for (int i = tid; i < NBLK; i += TPB)       // fixed order per thread
            lacc += __ldcg(&g_partial[i]);          // L2 reads, bypass stale L1

        #pragma unroll
        for (int off = 16; off > 0; off >>= 1)
            lacc += __shfl_xor_sync(0xFFFFFFFFu, lacc, off);

        __shared__ float s_fin[TPB / 32];
        if (lane == 0) s_fin[wid] = lacc;
        __syncthreads();

        if (tid == 0) {
            float total = 0.0f;
            #pragma unroll
            for (int w = 0; w < TPB / 32; w++) total += s_fin[w];
            const float clipped_zeros =
                (float)BATCH * (float)(NUM_CLASSES - 1) * 1e-12f;
            out[0] = (total + clipped_zeros) / (float)BATCH;
            g_done_count = 0;                        // reset for graph replay
        }
    }
}

extern "C" void kernel_launch(void* const* d_in, const int* in_sizes, int n_in,
                              void* d_out, int out_size) {
    const float* x       = (const float*)d_in[0];
    const int*   labels  = (const int*)d_in[1];   // width detected in-kernel
    const float* centers = (const float*)d_in[2];
    float*       out     = (float*)d_out;

    center_loss_kernel<<<NBLK, TPB>>>(x, labels, centers, out);
}